// round 8
// baseline (speedup 1.0000x reference)
#include <cuda_runtime.h>
#include <math.h>

// T=4096, B=4, S=16 -> 64 sequences; F=64, CH=97 (16 B + 16 C + 1 A + 64 X),
// K=5, CHUNK=64, 64 chunks, N_state=16, P=64 (collapsed via red_w projection).
// Conv as tf32 mma GEMM [64 t][320 fk][104 chp]; Gram G=C*B^T on tensor cores.
// 512-thread blocks: 16 warps/SM to hide LDS/MMA latency (smem-limited to 1 block/SM).

#define NSEQ   64
#define T_TOT  4096
#define NCHUNK 64
#define TPB    4

__device__ __forceinline__ unsigned tf32r(float x) {
    unsigned u; asm("cvt.rna.tf32.f32 %0,%1;" : "=r"(u) : "f"(x)); return u;
}
__device__ __forceinline__ float clip20(float v) { return fminf(fmaxf(v, -20.f), 20.f); }
__device__ __forceinline__ void cpa4(unsigned dst, const float* src, int sz) {
    asm volatile("cp.async.ca.shared.global [%0],[%1],4,%2;" :: "r"(dst), "l"(src), "r"(sz));
}

// ---------- device scratch ----------
__device__ float g_wB[320 * 104];             // [kk][chp], tf32, zero-pad ch>=97
__device__ float g_C[T_TOT * NSEQ * 16];      // [t][n][16]
__device__ float g_cum[T_TOT * NSEQ];         // [t][n]
__device__ float g_base[T_TOT * NSEQ];        // [t][n]
__device__ float g_sr[NSEQ * NCHUNK * 16];
__device__ float g_dch[NSEQ * NCHUNK];
__device__ float g_hr[NCHUNK * NSEQ * 16];    // [c][n][16]

// ---------- K0: build B matrix ----------
__global__ void k_wt(const float* __restrict__ w) {
    int i = blockIdx.x * blockDim.x + threadIdx.x;
    if (i < 320 * 104) {
        int kk = i / 104, chp = i % 104;
        int k = kk >> 6, f = kk & 63;
        float v = (chp < 97) ? w[chp * 320 + f * 5 + k] : 0.f;
        g_wB[i] = __uint_as_float(tf32r(v));
    }
}

// ---------- shared layout (floats) ----------
#define WB_O    0          // 33280
#define XS0_O   33280      // 64*72
#define XS1_O   37888      // 64*72
#define SX_O    42496      // 64*65
#define SB_O    46656      // 64*17
#define SC_O    47744      // 64*17
#define SG_O    48832      // 64*65
#define SA_O    52992
#define SCOEF_O 53056
#define SCUM_O  53120
#define SWS_O   53184
#define SDEC_O  53248
#define SDX_O   53312
#define SYD_O   53376      // 448 (7-way)
#define SSR_O   53824      // 64
#define SRW_O   53888
#define SPW_O   53952
#define SCB_O   54016      // 104
#define SMEMF   54120      // 216480 bytes

// ---------- K1 ----------
__global__ __launch_bounds__(512, 1) void k_main(
    const float* __restrict__ x,
    const float* __restrict__ conv_b,
    const float* __restrict__ pass_w,
    const float* __restrict__ pass_b,
    const float* __restrict__ red_w,
    const float* __restrict__ red_b,
    const float* __restrict__ dt_param)
{
    extern __shared__ float sm[];
    const int tid  = threadIdx.x;
    const int lane = tid & 31;
    const int wid  = tid >> 5;          // 16 warps
    const int n = blockIdx.y;
    const int b = n >> 4, s = n & 15;

    for (int i = tid; i < 33280 / 4; i += 512)
        ((float4*)(sm + WB_O))[i] = ((const float4*)g_wB)[i];
    if (tid < 64) { sm[SRW_O + tid] = red_w[tid]; sm[SPW_O + tid] = pass_w[tid]; }
    if (tid >= 64 && tid < 168) sm[SCB_O + (tid - 64)] = (tid - 64 < 97) ? conv_b[tid - 64] : 0.f;
    const float dt = log1pf(expf(dt_param[0])) + 0.01f;
    const float pb = pass_b[0], rb = red_b[0];

    // conv roles: mtile = wid>>2 (16 t rows each), nset = wid&3 (col groups)
    const int mtile = wid >> 2;
    const int nset  = wid & 3;
    const int nt    = nset ? 3 : 4;
    const int nb8   = (nset ? (4 + 3 * (nset - 1)) : 0) * 8;
    const int lc = lane & 3, lr = lane >> 2;

    const int chunk0 = blockIdx.x * TPB;

    // prologue: cp.async x tile of chunk0 into XS0
    {
        const int t0g = chunk0 * 64 - 4;
        for (int i = tid; i < 68 * 64; i += 512) {
            int lt = i >> 6, f = i & 63;
            int tg = t0g + lt;
            unsigned dst = (unsigned)__cvta_generic_to_shared(sm + XS0_O + f * 72 + lt);
            cpa4(dst, x + ((tg * 4 + b) * 16 + s) * 64 + f, (tg >= 0) ? 4 : 0);
        }
        asm volatile("cp.async.commit_group;" ::: "memory");
    }

    for (int it = 0; it < TPB; ++it) {
        const int chunk = chunk0 + it;
        const int cur_o = (it & 1) ? XS1_O : XS0_O;
        asm volatile("cp.async.wait_group 0;" ::: "memory");
        __syncthreads();

        if (it + 1 < TPB) {
            const int t0g = (chunk + 1) * 64 - 4;
            const int nxt_o = (it & 1) ? XS0_O : XS1_O;
            for (int i = tid; i < 68 * 64; i += 512) {
                int lt = i >> 6, f = i & 63;
                int tg = t0g + lt;
                unsigned dst = (unsigned)__cvta_generic_to_shared(sm + nxt_o + f * 72 + lt);
                cpa4(dst, x + ((tg * 4 + b) * 16 + s) * 64 + f, 4);
            }
            asm volatile("cp.async.commit_group;" ::: "memory");
        }

        // in-place tf32 rounding of current tile
        for (int i = tid; i < 68 * 64; i += 512) {
            int lt = i >> 6, f = i & 63;
            float* p = sm + cur_o + f * 72 + lt;
            *p = __uint_as_float(tf32r(*p));
        }
        __syncthreads();

        // ---- conv MMA: warp does 1 mtile x nt ntiles ----
        float acc[4][4];
#pragma unroll
        for (int q = 0; q < 4; ++q)
#pragma unroll
            for (int e = 0; e < 4; ++e) acc[q][e] = 0.f;

        const unsigned* xs_u = (const unsigned*)(sm + cur_o);
        const unsigned* wb_u = (const unsigned*)(sm + WB_O);

        for (int ks = 0; ks < 40; ++ks) {
            const int kk0 = ks * 8;
            const unsigned* ap = xs_u + ((kk0 & 63) + lc) * 72 + (kk0 >> 6) + lr + mtile * 16;
            const unsigned* bp = wb_u + (kk0 + lc) * 104 + nb8 + lr;
            unsigned a0 = ap[0], a1 = ap[8], a2 = ap[288], a3 = ap[296];
#pragma unroll
            for (int q = 0; q < 4; ++q) {
                if (q < nt) {
                    unsigned b0 = bp[q * 8];
                    unsigned b1 = bp[q * 8 + 416];
                    asm volatile(
                        "mma.sync.aligned.m16n8k8.row.col.f32.tf32.tf32.f32 "
                        "{%0,%1,%2,%3},{%4,%5,%6,%7},{%8,%9},{%0,%1,%2,%3};"
                        : "+f"(acc[q][0]), "+f"(acc[q][1]), "+f"(acc[q][2]), "+f"(acc[q][3])
                        : "r"(a0), "r"(a1), "r"(a2), "r"(a3), "r"(b0), "r"(b1));
                }
            }
        }

        // ---- epilogue: bias + (v + sigmoid(v)) + scatter ----
#pragma unroll
        for (int q = 0; q < 4; ++q) {
            if (q < nt) {
                const int ch0 = nb8 + q * 8 + 2 * lc;
                const int t0r = mtile * 16 + lr;
#pragma unroll
                for (int e = 0; e < 4; ++e) {
                    const int ch = ch0 + (e & 1);
                    const int t  = t0r + (e >> 1) * 8;
                    float v = acc[q][e] + sm[SCB_O + ch];
                    float u = v + __fdividef(1.f, 1.f + __expf(-v));
                    if (ch < 16)       sm[SB_O + t * 17 + ch] = u;
                    else if (ch < 32)  sm[SC_O + t * 17 + (ch - 16)] = u;
                    else if (ch == 32) {
                        float A  = -fabsf(u);
                        float la = dt * A;
                        sm[SA_O + t]    = la;
                        sm[SCOEF_O + t] = (__expf(la) - 1.f) / (A + 1e-9f);
                    } else if (ch < 97) sm[SX_O + t * 65 + (ch - 33)] = u;
                }
            }
        }
        __syncthreads();

        // ---- concurrent: scan | xr/Dx | C export | Gram (8 warps) ----
        if (tid < 32) {
            float v0 = sm[SA_O + tid], v1 = sm[SA_O + 32 + tid];
#pragma unroll
            for (int o = 1; o < 32; o <<= 1) {
                float a0 = __shfl_up_sync(0xffffffffu, v0, o);
                float a1 = __shfl_up_sync(0xffffffffu, v1, o);
                if (tid >= o) { v0 += a0; v1 += a1; }
            }
            float tot0  = __shfl_sync(0xffffffffu, v0, 31);
            float cum_b = v1 + tot0;
            float tot   = __shfl_sync(0xffffffffu, cum_b, 31);
            sm[SCUM_O + tid]      = v0;
            sm[SCUM_O + 32 + tid] = cum_b;
            sm[SDEC_O + tid]      = __expf(clip20(tot - v0));
            sm[SDEC_O + 32 + tid] = __expf(clip20(tot - cum_b));
            if (tid == 31) g_dch[n * 64 + chunk] = __expf(clip20(tot));
        } else if (tid < 96) {
            int t = tid - 32;
            float xr = 0.f;
#pragma unroll
            for (int p = 0; p < 64; ++p) xr = fmaf(sm[SX_O + t * 65 + p], sm[SRW_O + p], xr);
            float dx = pb;
#pragma unroll
            for (int f = 0; f < 64; ++f) dx = fmaf(sm[cur_o + f * 72 + (t + 4)], sm[SPW_O + f], dx);
            sm[SWS_O + t] = xr * sm[SCOEF_O + t];
            sm[SDX_O + t] = dx;
        } else if (tid < 256) {
            for (int idx = tid - 96; idx < 1024; idx += 160) {
                int l = idx >> 4, i = idx & 15;
                g_C[(((chunk * 64 + l) * 64) + n) * 16 + i] = sm[SC_O + l * 17 + i];
            }
        } else {
            // Gram: warp w (0..7): mtile m = w>>1, ntiles qoff..qoff+3
            const int w = wid - 8;
            const int m = w >> 1;
            const int qoff = (w & 1) * 4;
            float g[4][4];
#pragma unroll
            for (int q = 0; q < 4; ++q)
#pragma unroll
                for (int e = 0; e < 4; ++e) g[q][e] = 0.f;
#pragma unroll
            for (int k0 = 0; k0 < 16; k0 += 8) {
                unsigned a0 = tf32r(sm[SC_O + (m * 16 + lr) * 17 + k0 + lc]);
                unsigned a1 = tf32r(sm[SC_O + (m * 16 + 8 + lr) * 17 + k0 + lc]);
                unsigned a2 = tf32r(sm[SC_O + (m * 16 + lr) * 17 + k0 + lc + 4]);
                unsigned a3 = tf32r(sm[SC_O + (m * 16 + 8 + lr) * 17 + k0 + lc + 4]);
#pragma unroll
                for (int qq = 0; qq < 4; ++qq) {
                    const int q = qoff + qq;
                    unsigned b0 = tf32r(sm[SB_O + (q * 8 + lr) * 17 + k0 + lc]);
                    unsigned b1 = tf32r(sm[SB_O + (q * 8 + lr) * 17 + k0 + lc + 4]);
                    asm volatile(
                        "mma.sync.aligned.m16n8k8.row.col.f32.tf32.tf32.f32 "
                        "{%0,%1,%2,%3},{%4,%5,%6,%7},{%8,%9},{%0,%1,%2,%3};"
                        : "+f"(g[qq][0]), "+f"(g[qq][1]), "+f"(g[qq][2]), "+f"(g[qq][3])
                        : "r"(a0), "r"(a1), "r"(a2), "r"(a3), "r"(b0), "r"(b1));
                }
            }
#pragma unroll
            for (int qq = 0; qq < 4; ++qq) {
                const int q = qoff + qq;
                sm[SG_O + (m * 16 + lr) * 65 + q * 8 + 2 * lc]         = g[qq][0];
                sm[SG_O + (m * 16 + lr) * 65 + q * 8 + 2 * lc + 1]     = g[qq][1];
                sm[SG_O + (m * 16 + 8 + lr) * 65 + q * 8 + 2 * lc]     = g[qq][2];
                sm[SG_O + (m * 16 + 8 + lr) * 65 + q * 8 + 2 * lc + 1] = g[qq][3];
            }
        }
        __syncthreads();

        // ---- y_diag (7-way over m) + projected state partials ----
        if (tid < 448) {
            int l = tid & 63, hh = tid >> 6;
            float cuml = sm[SCUM_O + l];
            float acc2 = 0.f;
            for (int m = hh; m <= l; m += 7)
                acc2 += sm[SG_O + l * 65 + m] * sm[SWS_O + m]
                      * __expf(clip20(cuml - sm[SCUM_O + m]));
            sm[SYD_O + hh * 64 + l] = acc2;
        } else {
            int j = tid - 448, i = j & 15, part = j >> 4;
            float acc2 = 0.f;
#pragma unroll
            for (int q = 0; q < 16; ++q) {
                int l = part * 16 + q;
                acc2 = fmaf(sm[SB_O + l * 17 + i], sm[SWS_O + l] * sm[SDEC_O + l], acc2);
            }
            sm[SSR_O + j] = acc2;
        }
        __syncthreads();

        // ---- finalize chunk ----
        if (tid < 64) {
            int t = chunk * 64 + tid;
            float dx   = sm[SDX_O + tid];
            float base = sm[SYD_O + tid] + sm[SYD_O + 64 + tid] + sm[SYD_O + 128 + tid]
                       + sm[SYD_O + 192 + tid] + sm[SYD_O + 256 + tid]
                       + sm[SYD_O + 320 + tid] + sm[SYD_O + 384 + tid] + rb
                       + (dx >= 0.f ? dx : 0.01f * dx);
            g_base[t * 64 + n] = base;
            g_cum[t * 64 + n]  = sm[SCUM_O + tid];
        } else if (tid < 80) {
            int i = tid - 64;
            g_sr[(n * 64 + chunk) * 16 + i] = sm[SSR_O + i] + sm[SSR_O + 16 + i]
                                            + sm[SSR_O + 32 + i] + sm[SSR_O + 48 + i];
        }
    }
}

// ---------- K2: inter-chunk recurrence ----------
__global__ void k_scan() {
    __shared__ float ssr[64 * 16];
    __shared__ float sdc[64];
    const int n = blockIdx.x, tid = threadIdx.x;
    for (int i = tid; i < 1024; i += 64) ssr[i] = g_sr[n * 1024 + i];
    sdc[tid] = g_dch[n * 64 + tid];
    __syncthreads();
    if (tid < 16) {
        float h = 0.f;
        for (int c = 0; c < 64; ++c) {
            g_hr[(c * 64 + n) * 16 + tid] = h;
            h = sdc[c] * h + ssr[c * 16 + tid];
        }
    }
}

// ---------- K3: out = base + exp(cum) * (C . hr) ----------
__global__ __launch_bounds__(256) void k_final(float* __restrict__ out) {
    __shared__ float hr[1024];
    const int chunk = blockIdx.x;
    const int lg = blockIdx.y;            // 0..15
    const int tid = threadIdx.x;
    for (int i = tid; i < 1024; i += 256) hr[i] = g_hr[chunk * 1024 + i];
    __syncthreads();
    const int nn = tid & 63;
    const int l = lg * 4 + (tid >> 6);
    const int t = chunk * 64 + l;
    const float4* Cp = (const float4*)(g_C + (t * 64 + nn) * 16);
    float4 c0 = Cp[0], c1 = Cp[1], c2 = Cp[2], c3 = Cp[3];
    const float* h = hr + nn * 16;
    float acc = c0.x*h[0] + c0.y*h[1] + c0.z*h[2] + c0.w*h[3]
              + c1.x*h[4] + c1.y*h[5] + c1.z*h[6] + c1.w*h[7]
              + c2.x*h[8] + c2.y*h[9] + c2.z*h[10] + c2.w*h[11]
              + c3.x*h[12] + c3.y*h[13] + c3.z*h[14] + c3.w*h[15];
    out[t * 64 + nn] = g_base[t * 64 + nn] + __expf(g_cum[t * 64 + nn]) * acc;
}

// ---------- launch ----------
extern "C" void kernel_launch(void* const* d_in, const int* in_sizes, int n_in,
                              void* d_out, int out_size) {
    const float* x        = (const float*)d_in[0];
    const float* conv_w   = (const float*)d_in[1];
    const float* conv_b   = (const float*)d_in[2];
    const float* pass_w   = (const float*)d_in[3];
    const float* pass_b   = (const float*)d_in[4];
    const float* red_w    = (const float*)d_in[5];
    const float* red_b    = (const float*)d_in[6];
    const float* dt_param = (const float*)d_in[7];
    float* out = (float*)d_out;

    const int smem_bytes = SMEMF * (int)sizeof(float);
    cudaFuncSetAttribute(k_main, cudaFuncAttributeMaxDynamicSharedMemorySize, smem_bytes);

    k_wt<<<(320 * 104 + 255) / 256, 256>>>(conv_w);
    k_main<<<dim3(NCHUNK / TPB, NSEQ), 512, smem_bytes>>>(x, conv_b, pass_w, pass_b,
                                                          red_w, red_b, dt_param);
    k_scan<<<NSEQ, 64>>>();
    k_final<<<dim3(NCHUNK, 16), 256>>>(out);
}

// round 9
// speedup vs baseline: 1.2888x; 1.2888x over previous
#include <cuda_runtime.h>
#include <cuda_fp16.h>
#include <math.h>

// T=4096, B=4, S=16 -> 64 sequences; F=64, CH=97 (16 B + 16 C + 1 A + 64 X),
// K=5, CHUNK=64, 64 chunks, N_state=16, P=64 (collapsed via red_w projection).
// Conv as fp16 m16n8k16 mma GEMM [64 t][320 fk][104 chp] (fp32 accum);
// Gram G=C*B^T also fp16 MMA. 256-thr blocks (R6 structure; R7 showed 512 regresses).

#define NSEQ   64
#define T_TOT  4096
#define NCHUNK 64
#define TPB    4

__device__ __forceinline__ float clip20(float v) { return fminf(fmaxf(v, -20.f), 20.f); }
__device__ __forceinline__ void cpa4(unsigned dst, const float* src, int sz) {
    asm volatile("cp.async.ca.shared.global [%0],[%1],4,%2;" :: "r"(dst), "l"(src), "r"(sz));
}

// ---------- device scratch ----------
__device__ __align__(16) __half g_wB16[104 * 328];  // [ch][kk=k*64+f] fp16, zero-padded
__device__ float g_C[T_TOT * NSEQ * 16];            // [t][n][16]
__device__ float g_cum[T_TOT * NSEQ];               // [t][n]
__device__ float g_base[T_TOT * NSEQ];              // [t][n]
__device__ float g_sr[NSEQ * NCHUNK * 16];
__device__ float g_dch[NSEQ * NCHUNK];
__device__ float g_hr[NCHUNK * NSEQ * 16];          // [c][n][16]

// ---------- K0: build fp16 weight matrix ----------
__global__ void k_wt(const float* __restrict__ w) {
    int i = blockIdx.x * blockDim.x + threadIdx.x;
    if (i < 104 * 328) {
        int ch = i / 328, kk = i % 328;
        int k = kk >> 6, f = kk & 63;
        float v = (ch < 97 && kk < 320) ? w[ch * 320 + f * 5 + k] : 0.f;
        g_wB16[i] = __float2half(v);
    }
}

// ---------- shared layout (float offsets; fp16 regions via casts) ----------
#define WB16_O  0          // 104*328 halves = 17056 floats
#define XS0_O   17056      // 64*72 fp32 staging buf 0
#define XS1_O   21664      // buf 1
#define XT_O    26272      // 68*72 halves = 2448 floats  (x transposed [lt][f] fp16)
#define SX_O    28720      // 64*65
#define SB_O    32880      // 64*17
#define SC_O    33968      // 64*17
#define SB16_O  35056      // 64*18 halves = 576 floats
#define SC16_O  35632      // 576
#define SG_O    36208      // 64*65
#define SA_O    40368
#define SCOEF_O 40432
#define SCUM_O  40496
#define SWS_O   40560
#define SDEC_O  40624
#define SDX_O   40688
#define SYD_O   40752      // 192 (3-way)
#define SSR_O   40944      // 64
#define SRW_O   41008
#define SPW_O   41072
#define SCB_O   41136      // 104
#define SMEMF   41240      // 164960 bytes

// ---------- K1 ----------
__global__ __launch_bounds__(256, 1) void k_main(
    const float* __restrict__ x,
    const float* __restrict__ conv_b,
    const float* __restrict__ pass_w,
    const float* __restrict__ pass_b,
    const float* __restrict__ red_w,
    const float* __restrict__ red_b,
    const float* __restrict__ dt_param)
{
    extern __shared__ float sm[];
    const int tid  = threadIdx.x;
    const int lane = tid & 31;
    const int wid  = tid >> 5;          // 8 warps
    const int n = blockIdx.y;
    const int b = n >> 4, s = n & 15;

    // weight tile (fp16) + small params, once per block
    for (int i = tid; i < 17056 / 4; i += 256)
        ((float4*)sm)[i] = ((const float4*)g_wB16)[i];
    if (tid < 64) { sm[SRW_O + tid] = red_w[tid]; sm[SPW_O + tid] = pass_w[tid]; }
    if (tid >= 64 && tid < 168) sm[SCB_O + (tid - 64)] = (tid - 64 < 97) ? conv_b[tid - 64] : 0.f;
    const float dt = log1pf(expf(dt_param[0])) + 0.01f;
    const float pb = pass_b[0], rb = red_b[0];

    // conv roles: mpair = wid>>2 (rows 0-31 / 32-63), nset = wid&3
    const int mpair = wid >> 2;
    const int nset  = wid & 3;
    const int nt    = nset ? 3 : 4;
    const int nb8   = (nset ? (4 + 3 * (nset - 1)) : 0) * 8;
    const int lc = lane & 3, lr = lane >> 2;

    const int chunk0 = blockIdx.x * TPB;

    // prologue: cp.async x tile of chunk0 into XS0
    {
        const int t0g = chunk0 * 64 - 4;
        for (int i = tid; i < 68 * 64; i += 256) {
            int lt = i >> 6, f = i & 63;
            int tg = t0g + lt;
            unsigned dst = (unsigned)__cvta_generic_to_shared(sm + XS0_O + f * 72 + lt);
            cpa4(dst, x + ((tg * 4 + b) * 16 + s) * 64 + f, (tg >= 0) ? 4 : 0);
        }
        asm volatile("cp.async.commit_group;" ::: "memory");
    }

    for (int it = 0; it < TPB; ++it) {
        const int chunk = chunk0 + it;
        const int cur_o = (it & 1) ? XS1_O : XS0_O;
        asm volatile("cp.async.wait_group 0;" ::: "memory");
        __syncthreads();

        if (it + 1 < TPB) {
            const int t0g = (chunk + 1) * 64 - 4;
            const int nxt_o = (it & 1) ? XS0_O : XS1_O;
            for (int i = tid; i < 68 * 64; i += 256) {
                int lt = i >> 6, f = i & 63;
                int tg = t0g + lt;
                unsigned dst = (unsigned)__cvta_generic_to_shared(sm + nxt_o + f * 72 + lt);
                cpa4(dst, x + ((tg * 4 + b) * 16 + s) * 64 + f, 4);
            }
            asm volatile("cp.async.commit_group;" ::: "memory");
        }

        // convert+transpose current tile to fp16: xt[lt][f], stride 72 halves
        {
            __half* xt = (__half*)(sm + XT_O);
            for (int i = tid; i < 68 * 64; i += 256) {
                int f = i & 63, lt = i >> 6;
                xt[lt * 72 + f] = __float2half(sm[cur_o + f * 72 + lt]);
            }
        }
        __syncthreads();

        // ---- conv MMA (fp16 m16n8k16): 20 k-steps ----
        float acc[2][4][4];
#pragma unroll
        for (int mt = 0; mt < 2; ++mt)
#pragma unroll
            for (int q = 0; q < 4; ++q)
#pragma unroll
                for (int e = 0; e < 4; ++e) acc[mt][q][e] = 0.f;

        const __half* xt = (const __half*)(sm + XT_O);
        const __half* wb = (const __half*)sm;

        for (int ks = 0; ks < 20; ++ks) {
            const int kk0 = ks * 16;
            const int sh = kk0 >> 6, f0 = kk0 & 63;
            const __half* ap = xt + (mpair * 32 + lr + sh) * 72 + f0 + 2 * lc;
            const __half* bp = wb + (nb8 + lr) * 328 + kk0 + 2 * lc;
            unsigned a[2][4];
#pragma unroll
            for (int mt = 0; mt < 2; ++mt) {
                const __half* am = ap + mt * 16 * 72;
                a[mt][0] = *(const unsigned*)(am);
                a[mt][1] = *(const unsigned*)(am + 8 * 72);
                a[mt][2] = *(const unsigned*)(am + 8);
                a[mt][3] = *(const unsigned*)(am + 8 * 72 + 8);
            }
#pragma unroll
            for (int q = 0; q < 4; ++q) {
                if (q < nt) {
                    unsigned b0 = *(const unsigned*)(bp + q * 8 * 328);
                    unsigned b1 = *(const unsigned*)(bp + q * 8 * 328 + 8);
#pragma unroll
                    for (int mt = 0; mt < 2; ++mt) {
                        asm volatile(
                            "mma.sync.aligned.m16n8k16.row.col.f32.f16.f16.f32 "
                            "{%0,%1,%2,%3},{%4,%5,%6,%7},{%8,%9},{%0,%1,%2,%3};"
                            : "+f"(acc[mt][q][0]), "+f"(acc[mt][q][1]),
                              "+f"(acc[mt][q][2]), "+f"(acc[mt][q][3])
                            : "r"(a[mt][0]), "r"(a[mt][1]), "r"(a[mt][2]), "r"(a[mt][3]),
                              "r"(b0), "r"(b1));
                    }
                }
            }
        }

        // ---- epilogue: bias + (v + sigmoid(v)) + scatter (+fp16 copies of B,C) ----
        {
            __half* b16 = (__half*)(sm + SB16_O);
            __half* c16 = (__half*)(sm + SC16_O);
#pragma unroll
            for (int mt = 0; mt < 2; ++mt) {
#pragma unroll
                for (int q = 0; q < 4; ++q) {
                    if (q < nt) {
                        const int ch0 = nb8 + q * 8 + 2 * lc;
                        const int t0r = mpair * 32 + mt * 16 + lr;
#pragma unroll
                        for (int e = 0; e < 4; ++e) {
                            const int ch = ch0 + (e & 1);
                            const int t  = t0r + (e >> 1) * 8;
                            float v = acc[mt][q][e] + sm[SCB_O + ch];
                            float u = v + __fdividef(1.f, 1.f + __expf(-v));
                            if (ch < 16) {
                                sm[SB_O + t * 17 + ch] = u;
                                b16[t * 18 + ch] = __float2half(u);
                            } else if (ch < 32) {
                                sm[SC_O + t * 17 + (ch - 16)] = u;
                                c16[t * 18 + (ch - 16)] = __float2half(u);
                            } else if (ch == 32) {
                                float A  = -fabsf(u);
                                float la = dt * A;
                                sm[SA_O + t]    = la;
                                sm[SCOEF_O + t] = (__expf(la) - 1.f) / (A + 1e-9f);
                            } else if (ch < 97) sm[SX_O + t * 65 + (ch - 33)] = u;
                        }
                    }
                }
            }
        }
        __syncthreads();

        // ---- concurrent: scan | xr/Dx | C export | Gram (4 warps, fp16 MMA) ----
        if (tid < 32) {
            float v0 = sm[SA_O + tid], v1 = sm[SA_O + 32 + tid];
#pragma unroll
            for (int o = 1; o < 32; o <<= 1) {
                float a0 = __shfl_up_sync(0xffffffffu, v0, o);
                float a1 = __shfl_up_sync(0xffffffffu, v1, o);
                if (tid >= o) { v0 += a0; v1 += a1; }
            }
            float tot0  = __shfl_sync(0xffffffffu, v0, 31);
            float cum_b = v1 + tot0;
            float tot   = __shfl_sync(0xffffffffu, cum_b, 31);
            sm[SCUM_O + tid]      = v0;
            sm[SCUM_O + 32 + tid] = cum_b;
            sm[SDEC_O + tid]      = __expf(clip20(tot - v0));
            sm[SDEC_O + 32 + tid] = __expf(clip20(tot - cum_b));
            if (tid == 31) g_dch[n * 64 + chunk] = __expf(clip20(tot));
        } else if (tid < 96) {
            int t = tid - 32;
            float xr = 0.f;
#pragma unroll
            for (int p = 0; p < 64; ++p) xr = fmaf(sm[SX_O + t * 65 + p], sm[SRW_O + p], xr);
            float dx = pb;
#pragma unroll
            for (int f = 0; f < 64; ++f) dx = fmaf(sm[cur_o + f * 72 + (t + 4)], sm[SPW_O + f], dx);
            sm[SWS_O + t] = xr * sm[SCOEF_O + t];
            sm[SDX_O + t] = dx;
        } else if (tid < 128) {
            for (int idx = tid - 96; idx < 1024; idx += 32) {
                int l = idx >> 4, i = idx & 15;
                g_C[(((chunk * 64 + l) * 64) + n) * 16 + i] = sm[SC_O + l * 17 + i];
            }
        } else {
            // Gram: G[l][m] = sum_i C[l][i]*B[m][i]; warp w = mtile, 8 ntiles, k=16
            const int w = wid - 4;
            const __half* c16 = (const __half*)(sm + SC16_O);
            const __half* b16 = (const __half*)(sm + SB16_O);
            const __half* capt = c16 + (w * 16 + lr) * 18 + 2 * lc;
            unsigned a0 = *(const unsigned*)(capt);
            unsigned a1 = *(const unsigned*)(capt + 8 * 18);
            unsigned a2 = *(const unsigned*)(capt + 8);
            unsigned a3 = *(const unsigned*)(capt + 8 * 18 + 8);
            float g[8][4];
#pragma unroll
            for (int q = 0; q < 8; ++q) {
                const __half* bq = b16 + (q * 8 + lr) * 18 + 2 * lc;
                unsigned b0 = *(const unsigned*)(bq);
                unsigned b1 = *(const unsigned*)(bq + 8);
                g[q][0] = g[q][1] = g[q][2] = g[q][3] = 0.f;
                asm volatile(
                    "mma.sync.aligned.m16n8k16.row.col.f32.f16.f16.f32 "
                    "{%0,%1,%2,%3},{%4,%5,%6,%7},{%8,%9},{%0,%1,%2,%3};"
                    : "+f"(g[q][0]), "+f"(g[q][1]), "+f"(g[q][2]), "+f"(g[q][3])
                    : "r"(a0), "r"(a1), "r"(a2), "r"(a3), "r"(b0), "r"(b1));
            }
#pragma unroll
            for (int q = 0; q < 8; ++q) {
                sm[SG_O + (w * 16 + lr) * 65 + q * 8 + 2 * lc]         = g[q][0];
                sm[SG_O + (w * 16 + lr) * 65 + q * 8 + 2 * lc + 1]     = g[q][1];
                sm[SG_O + (w * 16 + 8 + lr) * 65 + q * 8 + 2 * lc]     = g[q][2];
                sm[SG_O + (w * 16 + 8 + lr) * 65 + q * 8 + 2 * lc + 1] = g[q][3];
            }
        }
        __syncthreads();

        // ---- y_diag (3-way over m) + projected state partials ----
        if (tid < 192) {
            int l = tid & 63, hh = tid >> 6;
            float cuml = sm[SCUM_O + l];
            float acc2 = 0.f;
            for (int m = hh; m <= l; m += 3)
                acc2 += sm[SG_O + l * 65 + m] * sm[SWS_O + m]
                      * __expf(clip20(cuml - sm[SCUM_O + m]));
            sm[SYD_O + hh * 64 + l] = acc2;
        } else {
            int j = tid - 192, i = j & 15, part = j >> 4;
            float acc2 = 0.f;
#pragma unroll
            for (int q = 0; q < 16; ++q) {
                int l = part * 16 + q;
                acc2 = fmaf(sm[SB_O + l * 17 + i], sm[SWS_O + l] * sm[SDEC_O + l], acc2);
            }
            sm[SSR_O + j] = acc2;
        }
        __syncthreads();

        // ---- finalize chunk ----
        if (tid < 64) {
            int t = chunk * 64 + tid;
            float dx   = sm[SDX_O + tid];
            float base = sm[SYD_O + tid] + sm[SYD_O + 64 + tid] + sm[SYD_O + 128 + tid] + rb
                       + (dx >= 0.f ? dx : 0.01f * dx);
            g_base[t * 64 + n] = base;
            g_cum[t * 64 + n]  = sm[SCUM_O + tid];
        } else if (tid < 80) {
            int i = tid - 64;
            g_sr[(n * 64 + chunk) * 16 + i] = sm[SSR_O + i] + sm[SSR_O + 16 + i]
                                            + sm[SSR_O + 32 + i] + sm[SSR_O + 48 + i];
        }
    }
}

// ---------- K2: inter-chunk recurrence ----------
__global__ void k_scan() {
    __shared__ float ssr[64 * 16];
    __shared__ float sdc[64];
    const int n = blockIdx.x, tid = threadIdx.x;
    for (int i = tid; i < 1024; i += 64) ssr[i] = g_sr[n * 1024 + i];
    sdc[tid] = g_dch[n * 64 + tid];
    __syncthreads();
    if (tid < 16) {
        float h = 0.f;
        for (int c = 0; c < 64; ++c) {
            g_hr[(c * 64 + n) * 16 + tid] = h;
            h = sdc[c] * h + ssr[c * 16 + tid];
        }
    }
}

// ---------- K3: out = base + exp(cum) * (C . hr) ----------
__global__ __launch_bounds__(256) void k_final(float* __restrict__ out) {
    __shared__ float hr[1024];
    const int chunk = blockIdx.x;
    const int lg = blockIdx.y;            // 0..15
    const int tid = threadIdx.x;
    for (int i = tid; i < 1024; i += 256) hr[i] = g_hr[chunk * 1024 + i];
    __syncthreads();
    const int nn = tid & 63;
    const int l = lg * 4 + (tid >> 6);
    const int t = chunk * 64 + l;
    const float4* Cp = (const float4*)(g_C + (t * 64 + nn) * 16);
    float4 c0 = Cp[0], c1 = Cp[1], c2 = Cp[2], c3 = Cp[3];
    const float* h = hr + nn * 16;
    float acc = c0.x*h[0] + c0.y*h[1] + c0.z*h[2] + c0.w*h[3]
              + c1.x*h[4] + c1.y*h[5] + c1.z*h[6] + c1.w*h[7]
              + c2.x*h[8] + c2.y*h[9] + c2.z*h[10] + c2.w*h[11]
              + c3.x*h[12] + c3.y*h[13] + c3.z*h[14] + c3.w*h[15];
    out[t * 64 + nn] = g_base[t * 64 + nn] + __expf(g_cum[t * 64 + nn]) * acc;
}

// ---------- launch ----------
extern "C" void kernel_launch(void* const* d_in, const int* in_sizes, int n_in,
                              void* d_out, int out_size) {
    const float* x        = (const float*)d_in[0];
    const float* conv_w   = (const float*)d_in[1];
    const float* conv_b   = (const float*)d_in[2];
    const float* pass_w   = (const float*)d_in[3];
    const float* pass_b   = (const float*)d_in[4];
    const float* red_w    = (const float*)d_in[5];
    const float* red_b    = (const float*)d_in[6];
    const float* dt_param = (const float*)d_in[7];
    float* out = (float*)d_out;

    const int smem_bytes = SMEMF * (int)sizeof(float);
    cudaFuncSetAttribute(k_main, cudaFuncAttributeMaxDynamicSharedMemorySize, smem_bytes);

    k_wt<<<(104 * 328 + 255) / 256, 256>>>(conv_w);
    k_main<<<dim3(NCHUNK / TPB, NSEQ), 256, smem_bytes>>>(x, conv_b, pass_w, pass_b,
                                                          red_w, red_b, dt_param);
    k_scan<<<NSEQ, 64>>>();
    k_final<<<dim3(NCHUNK, 16), 256>>>(out);
}

// round 10
// speedup vs baseline: 1.7131x; 1.3292x over previous
#include <cuda_runtime.h>
#include <cuda_fp16.h>
#include <math.h>

// T=4096, B=4, S=16 -> 64 sequences; F=64, CH=97 (16 B + 16 C + 1 A + 64 X),
// K=5, CHUNK=64, 64 chunks, N_state=16, P=64 (collapsed via red_w projection).
// Conv as fp16 m16n8k16 MMA GEMM; Gram G=C*B^T in MMA registers (no smem roundtrip).
// smem 111KB -> 2 blocks/SM for cross-block latency hiding.

#define NSEQ   64
#define T_TOT  4096
#define NCHUNK 64
#define TPB    4

__device__ __forceinline__ float clip20(float v) { return fminf(fmaxf(v, -20.f), 20.f); }

// ---------- device scratch ----------
__device__ __align__(16) __half g_wB16[104 * 328];  // [ch][kk=k*64+f] fp16, zero-padded
__device__ float g_C[T_TOT * NSEQ * 16];            // [t][n][16]
__device__ float g_cum[T_TOT * NSEQ];               // [t][n]
__device__ float g_base[T_TOT * NSEQ];              // [t][n]
__device__ float g_sr[NSEQ * NCHUNK * 16];
__device__ float g_dch[NSEQ * NCHUNK];
__device__ float g_hr[NCHUNK * NSEQ * 16];          // [c][n][16]

// ---------- K0: build fp16 weight matrix ----------
__global__ void k_wt(const float* __restrict__ w) {
    int i = blockIdx.x * blockDim.x + threadIdx.x;
    if (i < 104 * 328) {
        int ch = i / 328, kk = i % 328;
        int k = kk >> 6, f = kk & 63;
        float v = (ch < 97 && kk < 320) ? w[ch * 320 + f * 5 + k] : 0.f;
        g_wB16[i] = __float2half(v);
    }
}

// ---------- shared layout (float offsets; fp16 regions via casts) ----------
#define WB16_O  0          // 104*328 halves = 17056 floats
#define XT_O    17056      // 68*72 halves = 2448 floats (x fp16, [lt][f] stride 72)
#define SX_O    19504      // 64*65 fp32 X channels
#define SC_O    23664      // 64*17 fp32
#define SB_O    24752      // 64*17 fp32
#define SB16_O  25840      // 64*18 halves = 576 floats
#define SC16_O  26416      // 576
#define SA_O    26992      // 64
#define SCOEF_O 27056
#define SCUM_O  27120
#define SWS_O   27184
#define SDEC_O  27248
#define SDX_O   27312
#define SYD_O   27376      // 64 (final y_diag, no partials)
#define SSR_O   27440      // 64
#define SRW_O   27504
#define SPW_O   27568
#define SCB_O   27632      // 104
#define SMEMF   27736      // 110944 bytes -> 2 blocks/SM

// ---------- K1 ----------
__global__ __launch_bounds__(256, 2) void k_main(
    const float* __restrict__ x,
    const float* __restrict__ conv_b,
    const float* __restrict__ pass_w,
    const float* __restrict__ pass_b,
    const float* __restrict__ red_w,
    const float* __restrict__ red_b,
    const float* __restrict__ dt_param)
{
    extern __shared__ float sm[];
    const int tid  = threadIdx.x;
    const int lane = tid & 31;
    const int wid  = tid >> 5;          // 8 warps
    const int n = blockIdx.y;
    const int b = n >> 4, s = n & 15;

    // weight tile (fp16) + small params, once per block
    for (int i = tid; i < 17056 / 4; i += 256)
        ((float4*)sm)[i] = ((const float4*)g_wB16)[i];
    if (tid < 64) { sm[SRW_O + tid] = red_w[tid]; sm[SPW_O + tid] = pass_w[tid]; }
    if (tid >= 64 && tid < 168) sm[SCB_O + (tid - 64)] = (tid - 64 < 97) ? conv_b[tid - 64] : 0.f;
    const float dt = log1pf(expf(dt_param[0])) + 0.01f;
    const float pb = pass_b[0], rb = red_b[0];

    // conv roles: mpair = wid>>2 (rows 0-31 / 32-63), nset = wid&3
    const int mpair = wid >> 2;
    const int nset  = wid & 3;
    const int nt    = nset ? 3 : 4;
    const int nb8   = (nset ? (4 + 3 * (nset - 1)) : 0) * 8;
    const int lc = lane & 3, lr = lane >> 2;

    const int chunk0 = blockIdx.x * TPB;
    __half* xt = (__half*)(sm + XT_O);

    for (int it = 0; it < TPB; ++it) {
        const int chunk = chunk0 + it;
        const int t0g = chunk * 64 - 4;

        // load x -> fp16 tile (coalesced LDG, convert, STS)
        for (int i = tid; i < 68 * 64; i += 256) {
            int lt = i >> 6, f = i & 63;
            int tg = t0g + lt;
            float v = (tg >= 0) ? x[((tg * 4 + b) * 16 + s) * 64 + f] : 0.f;
            xt[lt * 72 + f] = __float2half(v);
        }
        __syncthreads();

        // ---- conv MMA (fp16 m16n8k16): 20 k-steps ----
        float acc[2][4][4];
#pragma unroll
        for (int mt = 0; mt < 2; ++mt)
#pragma unroll
            for (int q = 0; q < 4; ++q)
#pragma unroll
                for (int e = 0; e < 4; ++e) acc[mt][q][e] = 0.f;

        const __half* wb = (const __half*)sm;

        for (int ks = 0; ks < 20; ++ks) {
            const int kk0 = ks * 16;
            const int sh = kk0 >> 6, f0 = kk0 & 63;
            const __half* ap = xt + (mpair * 32 + lr + sh) * 72 + f0 + 2 * lc;
            const __half* bp = wb + (nb8 + lr) * 328 + kk0 + 2 * lc;
            unsigned a[2][4];
#pragma unroll
            for (int mt = 0; mt < 2; ++mt) {
                const __half* am = ap + mt * 16 * 72;
                a[mt][0] = *(const unsigned*)(am);
                a[mt][1] = *(const unsigned*)(am + 8 * 72);
                a[mt][2] = *(const unsigned*)(am + 8);
                a[mt][3] = *(const unsigned*)(am + 8 * 72 + 8);
            }
#pragma unroll
            for (int q = 0; q < 4; ++q) {
                if (q < nt) {
                    unsigned b0 = *(const unsigned*)(bp + q * 8 * 328);
                    unsigned b1 = *(const unsigned*)(bp + q * 8 * 328 + 8);
#pragma unroll
                    for (int mt = 0; mt < 2; ++mt) {
                        asm volatile(
                            "mma.sync.aligned.m16n8k16.row.col.f32.f16.f16.f32 "
                            "{%0,%1,%2,%3},{%4,%5,%6,%7},{%8,%9},{%0,%1,%2,%3};"
                            : "+f"(acc[mt][q][0]), "+f"(acc[mt][q][1]),
                              "+f"(acc[mt][q][2]), "+f"(acc[mt][q][3])
                            : "r"(a[mt][0]), "r"(a[mt][1]), "r"(a[mt][2]), "r"(a[mt][3]),
                              "r"(b0), "r"(b1));
                    }
                }
            }
        }

        // ---- epilogue: bias + (v + sigmoid(v)) + scatter ----
        {
            __half* b16 = (__half*)(sm + SB16_O);
            __half* c16 = (__half*)(sm + SC16_O);
#pragma unroll
            for (int mt = 0; mt < 2; ++mt) {
#pragma unroll
                for (int q = 0; q < 4; ++q) {
                    if (q < nt) {
                        const int ch0 = nb8 + q * 8 + 2 * lc;
                        const int t0r = mpair * 32 + mt * 16 + lr;
#pragma unroll
                        for (int e = 0; e < 4; ++e) {
                            const int ch = ch0 + (e & 1);
                            const int t  = t0r + (e >> 1) * 8;
                            float v = acc[mt][q][e] + sm[SCB_O + ch];
                            float u = v + __fdividef(1.f, 1.f + __expf(-v));
                            if (ch < 16) {
                                sm[SB_O + t * 17 + ch] = u;
                                b16[t * 18 + ch] = __float2half(u);
                            } else if (ch < 32) {
                                sm[SC_O + t * 17 + (ch - 16)] = u;
                                c16[t * 18 + (ch - 16)] = __float2half(u);
                            } else if (ch == 32) {
                                float A  = -fabsf(u);
                                float la = dt * A;
                                sm[SA_O + t]    = la;
                                sm[SCOEF_O + t] = (__expf(la) - 1.f) / (A + 1e-9f);
                            } else if (ch < 97) sm[SX_O + t * 65 + (ch - 33)] = u;
                        }
                    }
                }
            }
        }
        __syncthreads();

        // ---- phase 1: scan | xr/Dx | C export | Gram MMA (regs persist) ----
        float g[8][4];
        if (tid < 32) {
            float v0 = sm[SA_O + tid], v1 = sm[SA_O + 32 + tid];
#pragma unroll
            for (int o = 1; o < 32; o <<= 1) {
                float a0 = __shfl_up_sync(0xffffffffu, v0, o);
                float a1 = __shfl_up_sync(0xffffffffu, v1, o);
                if (tid >= o) { v0 += a0; v1 += a1; }
            }
            float tot0  = __shfl_sync(0xffffffffu, v0, 31);
            float cum_b = v1 + tot0;
            float tot   = __shfl_sync(0xffffffffu, cum_b, 31);
            sm[SCUM_O + tid]      = v0;
            sm[SCUM_O + 32 + tid] = cum_b;
            sm[SDEC_O + tid]      = __expf(clip20(tot - v0));
            sm[SDEC_O + 32 + tid] = __expf(clip20(tot - cum_b));
            if (tid == 31) g_dch[n * 64 + chunk] = __expf(clip20(tot));
        } else if (tid < 96) {
            int t = tid - 32;
            float xr = 0.f;
#pragma unroll
            for (int p = 0; p < 64; ++p) xr = fmaf(sm[SX_O + t * 65 + p], sm[SRW_O + p], xr);
            // Dx from fp16 x tile (half2)
            const __half2* xrow = (const __half2*)(xt + (t + 4) * 72);
            float dx = pb;
#pragma unroll
            for (int f2 = 0; f2 < 32; ++f2) {
                float2 v = __half22float2(xrow[f2]);
                dx = fmaf(v.x, sm[SPW_O + 2 * f2], dx);
                dx = fmaf(v.y, sm[SPW_O + 2 * f2 + 1], dx);
            }
            sm[SWS_O + t] = xr * sm[SCOEF_O + t];
            sm[SDX_O + t] = dx;
        } else if (tid < 128) {
            for (int idx = tid - 96; idx < 1024; idx += 32) {
                int l = idx >> 4, i = idx & 15;
                g_C[(((chunk * 64 + l) * 64) + n) * 16 + i] = sm[SC_O + l * 17 + i];
            }
        } else {
            // Gram: G[l][m] = sum_i C[l][i]*B[m][i]; warp w = l-tile, 8 m-tiles, k=16
            const int w = wid - 4;
            const __half* c16 = (const __half*)(sm + SC16_O);
            const __half* b16 = (const __half*)(sm + SB16_O);
            const __half* capt = c16 + (w * 16 + lr) * 18 + 2 * lc;
            unsigned a0 = *(const unsigned*)(capt);
            unsigned a1 = *(const unsigned*)(capt + 8 * 18);
            unsigned a2 = *(const unsigned*)(capt + 8);
            unsigned a3 = *(const unsigned*)(capt + 8 * 18 + 8);
#pragma unroll
            for (int q = 0; q < 8; ++q) {
                const __half* bq = b16 + (q * 8 + lr) * 18 + 2 * lc;
                unsigned b0 = *(const unsigned*)(bq);
                unsigned b1 = *(const unsigned*)(bq + 8);
                g[q][0] = g[q][1] = g[q][2] = g[q][3] = 0.f;
                asm volatile(
                    "mma.sync.aligned.m16n8k16.row.col.f32.f16.f16.f32 "
                    "{%0,%1,%2,%3},{%4,%5,%6,%7},{%8,%9},{%0,%1,%2,%3};"
                    : "+f"(g[q][0]), "+f"(g[q][1]), "+f"(g[q][2]), "+f"(g[q][3])
                    : "r"(a0), "r"(a1), "r"(a2), "r"(a3), "r"(b0), "r"(b1));
            }
        }
        __syncthreads();

        // ---- phase 2: y_diag from Gram registers | state partials ----
        if (tid >= 128) {
            const int w = wid - 4;
            const int l0 = w * 16 + lr, l1 = l0 + 8;
            const float cl0 = sm[SCUM_O + l0], cl1 = sm[SCUM_O + l1];
            float acc0 = 0.f, acc1 = 0.f;
#pragma unroll
            for (int q = 0; q < 8; ++q) {
                const int m0 = q * 8 + 2 * lc, m1 = m0 + 1;
                const float w0 = sm[SWS_O + m0], w1 = sm[SWS_O + m1];
                const float c0 = sm[SCUM_O + m0], c1 = sm[SCUM_O + m1];
                float e00 = (m0 <= l0) ? __expf(clip20(cl0 - c0)) : 0.f;
                float e01 = (m1 <= l0) ? __expf(clip20(cl0 - c1)) : 0.f;
                float e10 = (m0 <= l1) ? __expf(clip20(cl1 - c0)) : 0.f;
                float e11 = (m1 <= l1) ? __expf(clip20(cl1 - c1)) : 0.f;
                acc0 = fmaf(g[q][0], w0 * e00, acc0);
                acc0 = fmaf(g[q][1], w1 * e01, acc0);
                acc1 = fmaf(g[q][2], w0 * e10, acc1);
                acc1 = fmaf(g[q][3], w1 * e11, acc1);
            }
            acc0 += __shfl_xor_sync(0xffffffffu, acc0, 1);
            acc0 += __shfl_xor_sync(0xffffffffu, acc0, 2);
            acc1 += __shfl_xor_sync(0xffffffffu, acc1, 1);
            acc1 += __shfl_xor_sync(0xffffffffu, acc1, 2);
            if (lc == 0) { sm[SYD_O + l0] = acc0; sm[SYD_O + l1] = acc1; }
        } else if (tid < 64) {
            int i = tid & 15, part = tid >> 4;
            float acc2 = 0.f;
#pragma unroll
            for (int q = 0; q < 16; ++q) {
                int l = part * 16 + q;
                acc2 = fmaf(sm[SB_O + l * 17 + i], sm[SWS_O + l] * sm[SDEC_O + l], acc2);
            }
            sm[SSR_O + tid] = acc2;
        }
        __syncthreads();

        // ---- phase 3: finalize chunk ----
        if (tid < 64) {
            int t = chunk * 64 + tid;
            float dx   = sm[SDX_O + tid];
            float base = sm[SYD_O + tid] + rb + (dx >= 0.f ? dx : 0.01f * dx);
            g_base[t * 64 + n] = base;
            g_cum[t * 64 + n]  = sm[SCUM_O + tid];
        } else if (tid < 80) {
            int i = tid - 64;
            g_sr[(n * 64 + chunk) * 16 + i] = sm[SSR_O + i] + sm[SSR_O + 16 + i]
                                            + sm[SSR_O + 32 + i] + sm[SSR_O + 48 + i];
        }
        __syncthreads();
    }
}

// ---------- K2: inter-chunk recurrence ----------
__global__ void k_scan() {
    __shared__ float ssr[64 * 16];
    __shared__ float sdc[64];
    const int n = blockIdx.x, tid = threadIdx.x;
    for (int i = tid; i < 1024; i += 64) ssr[i] = g_sr[n * 1024 + i];
    sdc[tid] = g_dch[n * 64 + tid];
    __syncthreads();
    if (tid < 16) {
        float h = 0.f;
        for (int c = 0; c < 64; ++c) {
            g_hr[(c * 64 + n) * 16 + tid] = h;
            h = sdc[c] * h + ssr[c * 16 + tid];
        }
    }
}

// ---------- K3: out = base + exp(cum) * (C . hr) ----------
__global__ __launch_bounds__(256) void k_final(float* __restrict__ out) {
    __shared__ float hr[1024];
    const int chunk = blockIdx.x;
    const int lg = blockIdx.y;            // 0..15
    const int tid = threadIdx.x;
    for (int i = tid; i < 1024; i += 256) hr[i] = g_hr[chunk * 1024 + i];
    __syncthreads();
    const int nn = tid & 63;
    const int l = lg * 4 + (tid >> 6);
    const int t = chunk * 64 + l;
    const float4* Cp = (const float4*)(g_C + (t * 64 + nn) * 16);
    float4 c0 = Cp[0], c1 = Cp[1], c2 = Cp[2], c3 = Cp[3];
    const float* h = hr + nn * 16;
    float acc = c0.x*h[0] + c0.y*h[1] + c0.z*h[2] + c0.w*h[3]
              + c1.x*h[4] + c1.y*h[5] + c1.z*h[6] + c1.w*h[7]
              + c2.x*h[8] + c2.y*h[9] + c2.z*h[10] + c2.w*h[11]
              + c3.x*h[12] + c3.y*h[13] + c3.z*h[14] + c3.w*h[15];
    out[t * 64 + nn] = g_base[t * 64 + nn] + __expf(g_cum[t * 64 + nn]) * acc;
}

// ---------- launch ----------
extern "C" void kernel_launch(void* const* d_in, const int* in_sizes, int n_in,
                              void* d_out, int out_size) {
    const float* x        = (const float*)d_in[0];
    const float* conv_w   = (const float*)d_in[1];
    const float* conv_b   = (const float*)d_in[2];
    const float* pass_w   = (const float*)d_in[3];
    const float* pass_b   = (const float*)d_in[4];
    const float* red_w    = (const float*)d_in[5];
    const float* red_b    = (const float*)d_in[6];
    const float* dt_param = (const float*)d_in[7];
    float* out = (float*)d_out;

    const int smem_bytes = SMEMF * (int)sizeof(float);
    cudaFuncSetAttribute(k_main, cudaFuncAttributeMaxDynamicSharedMemorySize, smem_bytes);

    k_wt<<<(104 * 328 + 255) / 256, 256>>>(conv_w);
    k_main<<<dim3(NCHUNK / TPB, NSEQ), 256, smem_bytes>>>(x, conv_b, pass_w, pass_b,
                                                          red_w, red_b, dt_param);
    k_scan<<<NSEQ, 64>>>();
    k_final<<<dim3(NCHUNK, 16), 256>>>(out);
}

// round 11
// speedup vs baseline: 2.2624x; 1.3206x over previous
#include <cuda_runtime.h>
#include <cuda_fp16.h>
#include <math.h>

// T=4096, B=4, S=16 -> 64 sequences; F=64, CH=97 (16 B + 16 C + 1 A + 64 X),
// K=5, CHUNK=64, 64 chunks, N_state=16, P=64 (collapsed via red_w projection).
// Persistent fp16-MMA conv kernel (weights loaded once per block), Gram in MMA regs,
// 2 blocks/SM (111KB smem), fp16 g_C to halve k_final traffic.

#define NSEQ   64
#define T_TOT  4096
#define NCHUNK 64

__device__ __forceinline__ float clip20(float v) { return fminf(fmaxf(v, -20.f), 20.f); }

// ---------- device scratch ----------
__device__ __align__(16) __half g_wB16[104 * 328];  // [ch][kk=k*64+f] fp16, zero-padded
__device__ __align__(16) __half g_Ch[T_TOT * NSEQ * 16]; // [t][n][16] fp16
__device__ float g_cum[T_TOT * NSEQ];               // [t][n]
__device__ float g_base[T_TOT * NSEQ];              // [t][n]
__device__ float g_sr[NSEQ * NCHUNK * 16];
__device__ float g_dch[NSEQ * NCHUNK];
__device__ float g_hr[NCHUNK * NSEQ * 16];          // [c][n][16]

// ---------- K0: build fp16 weight matrix ----------
__global__ void k_wt(const float* __restrict__ w) {
    int i = blockIdx.x * blockDim.x + threadIdx.x;
    if (i < 104 * 328) {
        int ch = i / 328, kk = i % 328;
        int k = kk >> 6, f = kk & 63;
        float v = (ch < 97 && kk < 320) ? w[ch * 320 + f * 5 + k] : 0.f;
        g_wB16[i] = __float2half(v);
    }
}

// ---------- shared layout (float offsets; fp16 regions via casts) ----------
#define WB16_O  0          // 104*328 halves = 17056 floats
#define XT_O    17056      // 68*72 halves = 2448 floats (x fp16, [lt][f] stride 72)
#define SX_O    19504      // 64*65 fp32 X channels
#define SC_O    23664      // 64*17 fp32
#define SB_O    24752      // 64*17 fp32
#define SB16_O  25840      // 64*18 halves = 576 floats
#define SC16_O  26416      // 576
#define SA_O    26992      // 64
#define SCOEF_O 27056
#define SCUM_O  27120
#define SWS_O   27184
#define SDEC_O  27248
#define SDX_O   27312
#define SYD_O   27376      // 64
#define SSR_O   27440      // 64
#define SRW_O   27504
#define SPW_O   27568
#define SCB_O   27632      // 104
#define SMEMF   27736      // 110944 bytes -> 2 blocks/SM

// ---------- K1: persistent ----------
__global__ __launch_bounds__(256, 2) void k_main(
    const float* __restrict__ x,
    const float* __restrict__ conv_b,
    const float* __restrict__ pass_w,
    const float* __restrict__ pass_b,
    const float* __restrict__ red_w,
    const float* __restrict__ red_b,
    const float* __restrict__ dt_param)
{
    extern __shared__ float sm[];
    const int tid  = threadIdx.x;
    const int lane = tid & 31;
    const int wid  = tid >> 5;          // 8 warps

    // weight tile (fp16) + small params: ONCE per persistent block
    for (int i = tid; i < 17056 / 4; i += 256)
        ((float4*)sm)[i] = ((const float4*)g_wB16)[i];
    if (tid < 64) { sm[SRW_O + tid] = red_w[tid]; sm[SPW_O + tid] = pass_w[tid]; }
    if (tid >= 64 && tid < 168) sm[SCB_O + (tid - 64)] = (tid - 64 < 97) ? conv_b[tid - 64] : 0.f;
    const float dt = log1pf(expf(dt_param[0])) + 0.01f;
    const float pb = pass_b[0], rb = red_b[0];
    __syncthreads();

    // conv roles: mtile = wid&3 (16 t rows), nhalf = wid>>2 (q 0..6 / 7..12)
    const int mtile = wid & 3;
    const int nhalf = wid >> 2;
    const int nq    = nhalf ? 6 : 7;
    const int qb    = nhalf * 7;
    const int lc = lane & 3, lr = lane >> 2;

    __half* xt = (__half*)(sm + XT_O);
    const __half* wb = (const __half*)sm;

    for (int u = blockIdx.x; u < NSEQ * NCHUNK; u += gridDim.x) {
        const int n = u & 63, chunk = u >> 6;
        const int b = n >> 4, s = n & 15;
        const int t0g = chunk * 64 - 4;

        // load x -> fp16 tile
        for (int i = tid; i < 68 * 64; i += 256) {
            int lt = i >> 6, f = i & 63;
            int tg = t0g + lt;
            float v = (tg >= 0) ? x[((tg * 4 + b) * 16 + s) * 64 + f] : 0.f;
            xt[lt * 72 + f] = __float2half(v);
        }
        __syncthreads();

        // ---- conv MMA (fp16 m16n8k16): 20 k-steps, <=7 n-tiles per warp ----
        float acc[7][4];
#pragma unroll
        for (int q = 0; q < 7; ++q)
#pragma unroll
            for (int e = 0; e < 4; ++e) acc[q][e] = 0.f;

        for (int ks = 0; ks < 20; ++ks) {
            const int kk0 = ks * 16;
            const int sh = kk0 >> 6, f0 = kk0 & 63;
            const __half* ap = xt + (mtile * 16 + lr + sh) * 72 + f0 + 2 * lc;
            unsigned a0 = *(const unsigned*)(ap);
            unsigned a1 = *(const unsigned*)(ap + 8 * 72);
            unsigned a2 = *(const unsigned*)(ap + 8);
            unsigned a3 = *(const unsigned*)(ap + 8 * 72 + 8);
            const __half* bp = wb + (qb * 8 + lr) * 328 + kk0 + 2 * lc;
#pragma unroll
            for (int qq = 0; qq < 7; ++qq) {
                if (qq < nq) {
                    unsigned b0 = *(const unsigned*)(bp + qq * 8 * 328);
                    unsigned b1 = *(const unsigned*)(bp + qq * 8 * 328 + 8);
                    asm volatile(
                        "mma.sync.aligned.m16n8k16.row.col.f32.f16.f16.f32 "
                        "{%0,%1,%2,%3},{%4,%5,%6,%7},{%8,%9},{%0,%1,%2,%3};"
                        : "+f"(acc[qq][0]), "+f"(acc[qq][1]),
                          "+f"(acc[qq][2]), "+f"(acc[qq][3])
                        : "r"(a0), "r"(a1), "r"(a2), "r"(a3), "r"(b0), "r"(b1));
                }
            }
        }

        // ---- epilogue: bias + (v + sigmoid(v)) + scatter ----
        {
            __half* b16 = (__half*)(sm + SB16_O);
            __half* c16 = (__half*)(sm + SC16_O);
#pragma unroll
            for (int qq = 0; qq < 7; ++qq) {
                if (qq < nq) {
                    const int ch0 = (qb + qq) * 8 + 2 * lc;
                    const int t0r = mtile * 16 + lr;
#pragma unroll
                    for (int e = 0; e < 4; ++e) {
                        const int ch = ch0 + (e & 1);
                        const int t  = t0r + (e >> 1) * 8;
                        float v = acc[qq][e] + sm[SCB_O + ch];
                        float uu = v + __fdividef(1.f, 1.f + __expf(-v));
                        if (ch < 16) {
                            sm[SB_O + t * 17 + ch] = uu;
                            b16[t * 18 + ch] = __float2half(uu);
                        } else if (ch < 32) {
                            sm[SC_O + t * 17 + (ch - 16)] = uu;
                            c16[t * 18 + (ch - 16)] = __float2half(uu);
                        } else if (ch == 32) {
                            float A  = -fabsf(uu);
                            float la = dt * A;
                            sm[SA_O + t]    = la;
                            sm[SCOEF_O + t] = (__expf(la) - 1.f) / (A + 1e-9f);
                        } else if (ch < 97) sm[SX_O + t * 65 + (ch - 33)] = uu;
                    }
                }
            }
        }
        __syncthreads();

        // ---- phase 1: scan | xr/Dx | C export | Gram MMA (regs persist) ----
        float g[8][4];
        if (tid < 32) {
            float v0 = sm[SA_O + tid], v1 = sm[SA_O + 32 + tid];
#pragma unroll
            for (int o = 1; o < 32; o <<= 1) {
                float a0 = __shfl_up_sync(0xffffffffu, v0, o);
                float a1 = __shfl_up_sync(0xffffffffu, v1, o);
                if (tid >= o) { v0 += a0; v1 += a1; }
            }
            float tot0  = __shfl_sync(0xffffffffu, v0, 31);
            float cum_b = v1 + tot0;
            float tot   = __shfl_sync(0xffffffffu, cum_b, 31);
            sm[SCUM_O + tid]      = v0;
            sm[SCUM_O + 32 + tid] = cum_b;
            sm[SDEC_O + tid]      = __expf(clip20(tot - v0));
            sm[SDEC_O + 32 + tid] = __expf(clip20(tot - cum_b));
            if (tid == 31) g_dch[n * 64 + chunk] = __expf(clip20(tot));
        } else if (tid < 96) {
            int t = tid - 32;
            float xr = 0.f;
#pragma unroll
            for (int p = 0; p < 64; ++p) xr = fmaf(sm[SX_O + t * 65 + p], sm[SRW_O + p], xr);
            const __half2* xrow = (const __half2*)(xt + (t + 4) * 72);
            float dx = pb;
#pragma unroll
            for (int f2 = 0; f2 < 32; ++f2) {
                float2 v = __half22float2(xrow[f2]);
                dx = fmaf(v.x, sm[SPW_O + 2 * f2], dx);
                dx = fmaf(v.y, sm[SPW_O + 2 * f2 + 1], dx);
            }
            sm[SWS_O + t] = xr * sm[SCOEF_O + t];
            sm[SDX_O + t] = dx;
        } else if (tid < 128) {
            const __half* c16 = (const __half*)(sm + SC16_O);
            for (int idx = tid - 96; idx < 1024; idx += 32) {
                int l = idx >> 4, i = idx & 15;
                g_Ch[(((chunk * 64 + l) * 64) + n) * 16 + i] = c16[l * 18 + i];
            }
        } else {
            // Gram: G[l][m] = sum_i C[l][i]*B[m][i]; warp w = l-tile, 8 m-tiles
            const int w = wid - 4;
            const __half* c16 = (const __half*)(sm + SC16_O);
            const __half* b16 = (const __half*)(sm + SB16_O);
            const __half* capt = c16 + (w * 16 + lr) * 18 + 2 * lc;
            unsigned a0 = *(const unsigned*)(capt);
            unsigned a1 = *(const unsigned*)(capt + 8 * 18);
            unsigned a2 = *(const unsigned*)(capt + 8);
            unsigned a3 = *(const unsigned*)(capt + 8 * 18 + 8);
#pragma unroll
            for (int q = 0; q < 8; ++q) {
                const __half* bq = b16 + (q * 8 + lr) * 18 + 2 * lc;
                unsigned b0 = *(const unsigned*)(bq);
                unsigned b1 = *(const unsigned*)(bq + 8);
                g[q][0] = g[q][1] = g[q][2] = g[q][3] = 0.f;
                asm volatile(
                    "mma.sync.aligned.m16n8k16.row.col.f32.f16.f16.f32 "
                    "{%0,%1,%2,%3},{%4,%5,%6,%7},{%8,%9},{%0,%1,%2,%3};"
                    : "+f"(g[q][0]), "+f"(g[q][1]), "+f"(g[q][2]), "+f"(g[q][3])
                    : "r"(a0), "r"(a1), "r"(a2), "r"(a3), "r"(b0), "r"(b1));
            }
        }
        __syncthreads();

        // ---- phase 2: y_diag from Gram registers | state partials ----
        if (tid >= 128) {
            const int w = wid - 4;
            const int l0 = w * 16 + lr, l1 = l0 + 8;
            const float cl0 = sm[SCUM_O + l0], cl1 = sm[SCUM_O + l1];
            float acc0 = 0.f, acc1 = 0.f;
#pragma unroll
            for (int q = 0; q < 8; ++q) {
                const int m0 = q * 8 + 2 * lc, m1 = m0 + 1;
                const float w0 = sm[SWS_O + m0], w1 = sm[SWS_O + m1];
                const float c0 = sm[SCUM_O + m0], c1 = sm[SCUM_O + m1];
                float e00 = (m0 <= l0) ? __expf(clip20(cl0 - c0)) : 0.f;
                float e01 = (m1 <= l0) ? __expf(clip20(cl0 - c1)) : 0.f;
                float e10 = (m0 <= l1) ? __expf(clip20(cl1 - c0)) : 0.f;
                float e11 = (m1 <= l1) ? __expf(clip20(cl1 - c1)) : 0.f;
                acc0 = fmaf(g[q][0], w0 * e00, acc0);
                acc0 = fmaf(g[q][1], w1 * e01, acc0);
                acc1 = fmaf(g[q][2], w0 * e10, acc1);
                acc1 = fmaf(g[q][3], w1 * e11, acc1);
            }
            acc0 += __shfl_xor_sync(0xffffffffu, acc0, 1);
            acc0 += __shfl_xor_sync(0xffffffffu, acc0, 2);
            acc1 += __shfl_xor_sync(0xffffffffu, acc1, 1);
            acc1 += __shfl_xor_sync(0xffffffffu, acc1, 2);
            if (lc == 0) { sm[SYD_O + l0] = acc0; sm[SYD_O + l1] = acc1; }
        } else if (tid < 64) {
            int i = tid & 15, part = tid >> 4;
            float acc2 = 0.f;
#pragma unroll
            for (int q = 0; q < 16; ++q) {
                int l = part * 16 + q;
                acc2 = fmaf(sm[SB_O + l * 17 + i], sm[SWS_O + l] * sm[SDEC_O + l], acc2);
            }
            sm[SSR_O + tid] = acc2;
        }
        __syncthreads();

        // ---- phase 3: finalize chunk ----
        if (tid < 64) {
            int t = chunk * 64 + tid;
            float dx   = sm[SDX_O + tid];
            float base = sm[SYD_O + tid] + rb + (dx >= 0.f ? dx : 0.01f * dx);
            g_base[t * 64 + n] = base;
            g_cum[t * 64 + n]  = sm[SCUM_O + tid];
        } else if (tid < 80) {
            int i = tid - 64;
            g_sr[(n * 64 + chunk) * 16 + i] = sm[SSR_O + i] + sm[SSR_O + 16 + i]
                                            + sm[SSR_O + 32 + i] + sm[SSR_O + 48 + i];
        }
        __syncthreads();
    }
}

// ---------- K2: inter-chunk recurrence ----------
__global__ void k_scan() {
    __shared__ float ssr[64 * 16];
    __shared__ float sdc[64];
    const int n = blockIdx.x, tid = threadIdx.x;
    for (int i = tid; i < 1024; i += 64) ssr[i] = g_sr[n * 1024 + i];
    sdc[tid] = g_dch[n * 64 + tid];
    __syncthreads();
    if (tid < 16) {
        float h = 0.f;
        for (int c = 0; c < 64; ++c) {
            g_hr[(c * 64 + n) * 16 + tid] = h;
            h = sdc[c] * h + ssr[c * 16 + tid];
        }
    }
}

// ---------- K3: out = base + exp(cum) * (C . hr), fp16 C ----------
__global__ __launch_bounds__(256) void k_final(float* __restrict__ out) {
    __shared__ float hr[1024];
    const int chunk = blockIdx.x;
    const int lg = blockIdx.y;            // 0..15
    const int tid = threadIdx.x;
    for (int i = tid; i < 1024; i += 256) hr[i] = g_hr[chunk * 1024 + i];
    __syncthreads();
    const int nn = tid & 63;
    const int l = lg * 4 + (tid >> 6);
    const int t = chunk * 64 + l;
    const __half2* Cp = (const __half2*)(g_Ch + (t * 64 + nn) * 16);
    const float* h = hr + nn * 16;
    float acc = 0.f;
#pragma unroll
    for (int i2 = 0; i2 < 8; ++i2) {
        float2 c = __half22float2(Cp[i2]);
        acc = fmaf(c.x, h[2 * i2], acc);
        acc = fmaf(c.y, h[2 * i2 + 1], acc);
    }
    out[t * 64 + nn] = g_base[t * 64 + nn] + __expf(g_cum[t * 64 + nn]) * acc;
}

// ---------- launch ----------
extern "C" void kernel_launch(void* const* d_in, const int* in_sizes, int n_in,
                              void* d_out, int out_size) {
    const float* x        = (const float*)d_in[0];
    const float* conv_w   = (const float*)d_in[1];
    const float* conv_b   = (const float*)d_in[2];
    const float* pass_w   = (const float*)d_in[3];
    const float* pass_b   = (const float*)d_in[4];
    const float* red_w    = (const float*)d_in[5];
    const float* red_b    = (const float*)d_in[6];
    const float* dt_param = (const float*)d_in[7];
    float* out = (float*)d_out;

    int sms = 148;
    cudaDeviceGetAttribute(&sms, cudaDevAttrMultiProcessorCount, 0);
    const int nblocks = 2 * sms;   // persistent: exactly resident capacity

    const int smem_bytes = SMEMF * (int)sizeof(float);
    cudaFuncSetAttribute(k_main, cudaFuncAttributeMaxDynamicSharedMemorySize, smem_bytes);

    k_wt<<<(104 * 328 + 255) / 256, 256>>>(conv_w);
    k_main<<<nblocks, 256, smem_bytes>>>(x, conv_b, pass_w, pass_b,
                                         red_w, red_b, dt_param);
    k_scan<<<NSEQ, 64>>>();
    k_final<<<dim3(NCHUNK, 16), 256>>>(out);
}